// round 6
// baseline (speedup 1.0000x reference)
#include <cuda_runtime.h>

// Problem sizes
#define Bn   256
#define Tn   512
#define EMBn 64
#define HSn  512
#define VSn  128

// Shape: 8 row-groups (32 batch rows each) x 16 col-tiles (32 hidden cols) = 128 CTAs
#define GRID   128
#define NGROUP 8
#define GSIZE  16
#define BLOCKT 256
#define KC     64          // K-chunk staged through SMEM
#define KTOT   1600        // concat K: Wih0(64)+Whh0(512)+Wih1(512)+Whh1(512)
#define WPAD   1604        // Wt row stride (floats): mod 32 == 4 -> balanced banks
#define APAD   68          // A buffer row stride (floats)
#define FCPAD  36          // FC smem stride

#define SMEM_FLOATS (32 * WPAD + 2 * 32 * APAD)
#define SMEM_BYTES  (SMEM_FLOATS * 4)        // 222,720 B

typedef unsigned long long ull;

// Packed dual-FMA: (acc.lo,acc.hi) += (a.lo,a.hi)*(b.lo,b.hi)
#define FFMA2(acc, a, b) \
    asm("fma.rn.f32x2 %0, %1, %2, %0;" : "+l"(acc) : "l"(a), "l"(b))

__device__ __forceinline__ float hsum2(ull v) {
    float lo, hi;
    asm("mov.b64 {%0, %1}, %2;" : "=f"(lo), "=f"(hi) : "l"(v));
    return lo + hi;
}

// -------- persistent device state (no allocations; __device__ globals) -------
__device__ float g_h0[2][Bn * HSn];                 // ping-pong h0
__device__ float g_outs[(size_t)Tn * Bn * HSn];     // h1 history [t][b][hs]
struct PadCnt { unsigned v; unsigned pad[31]; };
__device__ PadCnt g_gcnt[NGROUP];                   // per-group arrival counters
__device__ volatile unsigned g_gphase[NGROUP * 32]; // per-group phase (128B strided)
__device__ unsigned g_allcnt;                       // full-grid barrier
__device__ volatile unsigned g_allphase;

__device__ __forceinline__ void group_sync(int g) {
    __threadfence();
    __syncthreads();
    if (threadIdx.x == 0) {
        unsigned ph = g_gphase[g * 32];
        if (atomicAdd(&g_gcnt[g].v, 1u) == GSIZE - 1u) {
            g_gcnt[g].v = 0u;
            __threadfence();
            g_gphase[g * 32] = ph + 1u;
        } else {
            while (g_gphase[g * 32] == ph) { }
        }
    }
    __syncthreads();
}

__device__ __forceinline__ void grid_sync_all() {
    __threadfence();
    __syncthreads();
    if (threadIdx.x == 0) {
        unsigned ph = g_allphase;
        if (atomicAdd(&g_allcnt, 1u) == GRID - 1u) {
            g_allcnt = 0u;
            __threadfence();
            g_allphase = ph + 1u;
        } else {
            while (g_allphase == ph) { }
        }
    }
    __syncthreads();
}

// One KC=64 chunk: 2x2 micro-tile via packed f32x2 FMAs (accumulate along k-pairs).
__device__ __forceinline__ void chunk_fma2(const float* __restrict__ Ac,
                                           const float* __restrict__ W0,
                                           const float* __restrict__ W1,
                                           int ty,
                                           ull& a00, ull& a01, ull& a10, ull& a11) {
    #pragma unroll
    for (int k4 = 0; k4 < KC; k4 += 4) {
        ulonglong2 av0 = *(const ulonglong2*)(Ac + ty * APAD + k4);
        ulonglong2 av1 = *(const ulonglong2*)(Ac + (ty + 16) * APAD + k4);
        ulonglong2 bv0 = *(const ulonglong2*)(W0 + k4);
        ulonglong2 bv1 = *(const ulonglong2*)(W1 + k4);
        FFMA2(a00, av0.x, bv0.x); FFMA2(a00, av0.y, bv0.y);
        FFMA2(a01, av0.x, bv1.x); FFMA2(a01, av0.y, bv1.y);
        FFMA2(a10, av1.x, bv0.x); FFMA2(a10, av1.y, bv0.y);
        FFMA2(a11, av1.x, bv1.x); FFMA2(a11, av1.y, bv1.y);
    }
}

extern __shared__ float smem[];

__global__ void __launch_bounds__(BLOCKT, 1) rnn_persistent_kernel(
    const int*   __restrict__ x,
    const float* __restrict__ emb,
    const float* __restrict__ W_ih0, const float* __restrict__ b_ih0,
    const float* __restrict__ W_hh0, const float* __restrict__ b_hh0,
    const float* __restrict__ W_ih1, const float* __restrict__ b_ih1,
    const float* __restrict__ W_hh1, const float* __restrict__ b_hh1,
    const float* __restrict__ W_fc,  const float* __restrict__ b_fc,
    float* __restrict__ out)
{
    float* Wt = smem;                      // [32][WPAD] resident weight slice
    float* Ab = smem + 32 * WPAD;          // [2][32][APAD] A double buffer

    const int tid  = threadIdx.x;
    const int cta  = blockIdx.x;
    const int grp  = cta >> 4;
    const int row0 = grp * 32;             // batch rows owned by this group
    const int col0 = (cta & 15) * 32;      // hidden cols owned by this CTA

    // ---- load the CTA's weight slice once: Wt[c][k], k = concat index -------
    {
        const int c  = tid & 31;
        const int k8 = tid >> 5;
        for (int kb = 0; kb < KTOT; kb += 8) {
            int k = kb + k8;
            const float* src; int kr;
            if      (k < 64)   { src = W_ih0; kr = k; }
            else if (k < 576)  { src = W_hh0; kr = k - 64; }
            else if (k < 1088) { src = W_ih1; kr = k - 576; }
            else               { src = W_hh1; kr = k - 1088; }
            Wt[c * WPAD + k] = src[(size_t)kr * HSn + col0 + c];
        }
    }
    __syncthreads();

    // compute mapping (16x16 threads, 2x2 micro-tile)
    const int ty  = tid >> 4;              // 0..15 -> rows ty, ty+16
    const int tx  = tid & 15;              // 0..15 -> cols tx, tx+16
    const int ak4 = (tid & 15) * 4;        // A loader k offset (float4)

    const int r0g = row0 + ty, r1g = row0 + ty + 16;
    const int c0  = col0 + tx, c1  = col0 + tx + 16;
    const float bias0_0 = b_ih0[c0] + b_hh0[c0];
    const float bias0_1 = b_ih0[c1] + b_hh0[c1];
    const float bias1_0 = b_ih1[c0] + b_hh1[c0];
    const float bias1_1 = b_ih1[c1] + b_hh1[c1];

    const float* W0a = Wt + tx * WPAD;
    const float* W1a = Wt + (tx + 16) * WPAD;

    for (int t = 0; t < Tn; ++t) {
        const float* h0_prev = g_h0[(t & 1) ^ 1];
        float*       h0_cur  = g_h0[t & 1];
        const float* h1_prev = g_outs + (size_t)(t - 1) * Bn * HSn;  // valid t>0
        float*       h1_cur  = g_outs + (size_t)t * Bn * HSn;

        // =========== layer 0: h0 = tanh([emb | h0_prev] @ [Wih0;Whh0] + b)
        {
            const int nch = (t == 0) ? 1 : 9;   // t=0: h0_prev is zero, skip
            float4 p0, p1;
            {   // chunk 0 = embedding rows -> buf0 directly
                int xi0 = x[r0g * Tn + t];
                int xi1 = x[r1g * Tn + t];
                p0 = *(const float4*)&emb[xi0 * EMBn + ak4];
                p1 = *(const float4*)&emb[xi1 * EMBn + ak4];
                *(float4*)&Ab[ty * APAD + ak4]        = p0;
                *(float4*)&Ab[(ty + 16) * APAD + ak4] = p1;
            }
            if (nch > 1) {   // prefetch chunk 1 = h0_prev k=0
                p0 = __ldcg((const float4*)&h0_prev[(size_t)r0g * HSn + ak4]);
                p1 = __ldcg((const float4*)&h0_prev[(size_t)r1g * HSn + ak4]);
            }
            __syncthreads();

            ull a00 = 0ull, a01 = 0ull, a10 = 0ull, a11 = 0ull;
            #pragma unroll 1
            for (int c = 0; c < nch; ++c) {
                if (c + 1 < nch) {                     // store regs(c+1) -> buf^1
                    float* An = Ab + ((c + 1) & 1) * 32 * APAD;
                    *(float4*)&An[ty * APAD + ak4]        = p0;
                    *(float4*)&An[(ty + 16) * APAD + ak4] = p1;
                }
                if (c + 2 < nch) {                     // issue LDG for chunk c+2
                    int kb = (c + 1) * KC;             // h0_prev k = (ci-1)*64
                    p0 = __ldcg((const float4*)&h0_prev[(size_t)r0g * HSn + kb + ak4]);
                    p1 = __ldcg((const float4*)&h0_prev[(size_t)r1g * HSn + kb + ak4]);
                }
                chunk_fma2(Ab + (c & 1) * 32 * APAD, W0a + c * KC, W1a + c * KC,
                           ty, a00, a01, a10, a11);
                __syncthreads();
            }
            h0_cur[(size_t)r0g * HSn + c0] = tanhf(hsum2(a00) + bias0_0);
            h0_cur[(size_t)r0g * HSn + c1] = tanhf(hsum2(a01) + bias0_1);
            h0_cur[(size_t)r1g * HSn + c0] = tanhf(hsum2(a10) + bias0_0);
            h0_cur[(size_t)r1g * HSn + c1] = tanhf(hsum2(a11) + bias0_1);
        }
        group_sync(grp);   // h0_cur complete within group (also orders prev L1)

        // =========== layer 1: h1 = tanh([h0_cur | h1_prev] @ [Wih1;Whh1] + b)
        {
            const int nch = (t == 0) ? 8 : 16;  // t=0: h1_prev is zero, skip
            float4 p0, p1;
            {   // chunk 0 = h0_cur k=0 -> buf0 directly
                p0 = __ldcg((const float4*)&h0_cur[(size_t)r0g * HSn + ak4]);
                p1 = __ldcg((const float4*)&h0_cur[(size_t)r1g * HSn + ak4]);
                *(float4*)&Ab[ty * APAD + ak4]        = p0;
                *(float4*)&Ab[(ty + 16) * APAD + ak4] = p1;
            }
            {   // prefetch chunk 1 = h0_cur k=64
                p0 = __ldcg((const float4*)&h0_cur[(size_t)r0g * HSn + KC + ak4]);
                p1 = __ldcg((const float4*)&h0_cur[(size_t)r1g * HSn + KC + ak4]);
            }
            __syncthreads();

            ull d00 = 0ull, d01 = 0ull, d10 = 0ull, d11 = 0ull;
            #pragma unroll 1
            for (int c = 0; c < nch; ++c) {
                if (c + 1 < nch) {
                    float* An = Ab + ((c + 1) & 1) * 32 * APAD;
                    *(float4*)&An[ty * APAD + ak4]        = p0;
                    *(float4*)&An[(ty + 16) * APAD + ak4] = p1;
                }
                if (c + 2 < nch) {
                    const int ci = c + 2;
                    const float* hs = (ci < 8) ? h0_cur : h1_prev;
                    const int kb = (ci < 8) ? ci * KC : (ci - 8) * KC;
                    p0 = __ldcg((const float4*)&hs[(size_t)r0g * HSn + kb + ak4]);
                    p1 = __ldcg((const float4*)&hs[(size_t)r1g * HSn + kb + ak4]);
                }
                chunk_fma2(Ab + (c & 1) * 32 * APAD,
                           W0a + 576 + c * KC, W1a + 576 + c * KC,
                           ty, d00, d01, d10, d11);
                __syncthreads();
            }
            h1_cur[(size_t)r0g * HSn + c0] = tanhf(hsum2(d00) + bias1_0);
            h1_cur[(size_t)r0g * HSn + c1] = tanhf(hsum2(d01) + bias1_1);
            h1_cur[(size_t)r1g * HSn + c0] = tanhf(hsum2(d10) + bias1_0);
            h1_cur[(size_t)r1g * HSn + c1] = tanhf(hsum2(d11) + bias1_1);
        }
        // no barrier: next step's post-L0 group_sync transitively orders h1.
    }

    grid_sync_all();   // all h1 history visible chip-wide before FC

    // =========== final FC: logits[b,t,:] = h1[t,b,:] @ W_fc + b_fc ==========
    float* fcA = smem;                 // [64][FCPAD]
    float* fcB = smem + 64 * FCPAD;    // [128][FCPAD]

    const int lkk = tid & 31;
    const int lr  = tid >> 5;
    const int fty = tid >> 5;          // 0..7
    const int ftx = tid & 31;          // 0..31
    const int fj  = tid & 127;
    const int fkk = tid >> 7;
    const int NTILES = (Bn * Tn) / 64;

    for (int tile = cta; tile < NTILES; tile += GRID) {
        const int m0 = tile * 64;
        ull acc[8][4];
        #pragma unroll
        for (int ii = 0; ii < 8; ++ii)
            #pragma unroll
            for (int jj = 0; jj < 4; ++jj) acc[ii][jj] = 0ull;

        #pragma unroll 1
        for (int k0 = 0; k0 < HSn; k0 += 32) {
            __syncthreads();
            #pragma unroll
            for (int rr = lr; rr < 64; rr += 8)
                fcA[rr * FCPAD + lkk] =
                    g_outs[(size_t)(m0 + rr) * HSn + k0 + lkk];
            #pragma unroll
            for (int kx = fkk; kx < 32; kx += 2)
                fcB[fj * FCPAD + kx] = W_fc[(size_t)(k0 + kx) * VSn + fj];
            __syncthreads();
            #pragma unroll
            for (int k4 = 0; k4 < 32; k4 += 4) {
                ulonglong2 bv[4];
                #pragma unroll
                for (int jj = 0; jj < 4; ++jj)
                    bv[jj] = *(const ulonglong2*)&fcB[(ftx + 32 * jj) * FCPAD + k4];
                #pragma unroll
                for (int ii = 0; ii < 8; ++ii) {
                    ulonglong2 av = *(const ulonglong2*)&fcA[(fty + 8 * ii) * FCPAD + k4];
                    #pragma unroll
                    for (int jj = 0; jj < 4; ++jj) {
                        FFMA2(acc[ii][jj], av.x, bv[jj].x);
                        FFMA2(acc[ii][jj], av.y, bv[jj].y);
                    }
                }
            }
        }
        #pragma unroll
        for (int ii = 0; ii < 8; ++ii) {
            const int m  = m0 + fty + 8 * ii;
            const int tt = m >> 8;
            const int bb = m & 255;
            float* op = out + ((size_t)bb * Tn + tt) * VSn;
            #pragma unroll
            for (int jj = 0; jj < 4; ++jj) {
                const int c = ftx + 32 * jj;
                op[c] = hsum2(acc[ii][jj]) + b_fc[c];
            }
        }
        __syncthreads();
    }
}

extern "C" void kernel_launch(void* const* d_in, const int* in_sizes, int n_in,
                              void* d_out, int out_size) {
    const int*   x      = (const int*)  d_in[0];
    const float* emb    = (const float*)d_in[1];
    const float* W_ih0  = (const float*)d_in[2];
    const float* b_ih0  = (const float*)d_in[3];
    const float* W_hh0  = (const float*)d_in[4];
    const float* b_hh0  = (const float*)d_in[5];
    const float* W_ih1  = (const float*)d_in[6];
    const float* b_ih1  = (const float*)d_in[7];
    const float* W_hh1  = (const float*)d_in[8];
    const float* b_hh1  = (const float*)d_in[9];
    const float* W_fc   = (const float*)d_in[10];
    const float* b_fc   = (const float*)d_in[11];
    float* out = (float*)d_out;

    cudaFuncSetAttribute(rnn_persistent_kernel,
                         cudaFuncAttributeMaxDynamicSharedMemorySize, SMEM_BYTES);

    rnn_persistent_kernel<<<GRID, BLOCKT, SMEM_BYTES>>>(
        x, emb, W_ih0, b_ih0, W_hh0, b_hh0,
        W_ih1, b_ih1, W_hh1, b_hh1, W_fc, b_fc, out);
}

// round 7
// speedup vs baseline: 1.9874x; 1.9874x over previous
#include <cuda_runtime.h>
#include <cuda_fp16.h>

// Problem sizes
#define Bn   256
#define Tn   512
#define EMBn 64
#define HSn  512
#define VSn  128

// 8 row-groups (32 batch rows) x 16 col-tiles (32 hidden cols) = 128 CTAs
#define GRID   128
#define NGROUP 8
#define GSIZE  16
#define BLOCKT 256
#define KC     64            // K-chunk (= 4 k16 blocks; one per K-split warp)
#define WS     808           // W plane row stride in uint32 kpairs (800 + pad; 808%32==8)
#define SA     40            // A plane row stride in uint32 kpairs (32 + pad; 40%32==8)
#define APLANE (32 * SA)     // 1280 u32 per plane
#define ABUFSZ (2 * APLANE)  // hi+lo planes per buffer
#define REDSTRIDE 640        // epilogue reduction: per-warp float stride
#define FCPAD  36

#define SMEM_U32  (2 * 32 * WS + 2 * ABUFSZ)   // W(hi,lo) + A double buffer = 56832
#define SMEM_BYTES (SMEM_U32 * 4)              // 227,328 B (red region aliases A)

typedef unsigned int u32;

// -------- persistent device state ----------------------------------------
__device__ float g_h0[2][Bn * HSn];                 // ping-pong h0
__device__ float g_outs[(size_t)Tn * Bn * HSn];     // h1 history [t][b][hs]
struct PadCnt { unsigned v; unsigned pad[31]; };
__device__ PadCnt g_gcnt[NGROUP];
__device__ volatile unsigned g_gphase[NGROUP * 32];
__device__ unsigned g_allcnt;
__device__ volatile unsigned g_allphase;

__device__ __forceinline__ void group_sync(int g) {
    __threadfence();
    __syncthreads();
    if (threadIdx.x == 0) {
        unsigned ph = g_gphase[g * 32];
        if (atomicAdd(&g_gcnt[g].v, 1u) == GSIZE - 1u) {
            g_gcnt[g].v = 0u;
            __threadfence();
            g_gphase[g * 32] = ph + 1u;
        } else {
            while (g_gphase[g * 32] == ph) { }
        }
    }
    __syncthreads();
}

__device__ __forceinline__ void grid_sync_all() {
    __threadfence();
    __syncthreads();
    if (threadIdx.x == 0) {
        unsigned ph = g_allphase;
        if (atomicAdd(&g_allcnt, 1u) == GRID - 1u) {
            g_allcnt = 0u;
            __threadfence();
            g_allphase = ph + 1u;
        } else {
            while (g_allphase == ph) { }
        }
    }
    __syncthreads();
}

// -------- fp16 split + mma helpers ---------------------------------------
__device__ __forceinline__ void split2(float x, float y, u32& hi, u32& lo) {
    __half hx = __float2half_rn(x), hy = __float2half_rn(y);
    __half lx = __float2half_rn(x - __half2float(hx));
    __half ly = __float2half_rn(y - __half2float(hy));
    __half2 h = __halves2half2(hx, hy), l = __halves2half2(lx, ly);
    hi = *(u32*)&h; lo = *(u32*)&l;
}

__device__ __forceinline__ void mma16816(float c[4],
                                         u32 a0, u32 a1, u32 a2, u32 a3,
                                         u32 b0, u32 b1) {
    asm volatile(
        "mma.sync.aligned.m16n8k16.row.col.f32.f16.f16.f32 "
        "{%0,%1,%2,%3}, {%4,%5,%6,%7}, {%8,%9}, {%0,%1,%2,%3};"
        : "+f"(c[0]), "+f"(c[1]), "+f"(c[2]), "+f"(c[3])
        : "r"(a0), "r"(a1), "r"(a2), "r"(a3), "r"(b0), "r"(b1));
}

// Convert + store one float4 (4 consecutive k of a row) into A planes.
__device__ __forceinline__ void storeA(u32* Abase, int row, int pos0, int pos1,
                                       float4 v) {
    u32 h0, l0, h1, l1;
    split2(v.x, v.y, h0, l0);
    split2(v.z, v.w, h1, l1);
    Abase[row * SA + pos0]          = h0;
    Abase[APLANE + row * SA + pos0] = l0;
    Abase[row * SA + pos1]          = h1;
    Abase[APLANE + row * SA + pos1] = l1;
}

// One KC=64 chunk for this warp's k16 block: 4 n-blocks x 3 split-products.
__device__ __forceinline__ void chunk_mma(const u32* __restrict__ Abase,
                                          const u32* __restrict__ Whi,
                                          const u32* __restrict__ Wlo,
                                          int aoff0, int aoff1, int bbase,
                                          float acc[4][4]) {
    uint2 Ah0 = *(const uint2*)(Abase + aoff0);
    uint2 Ah1 = *(const uint2*)(Abase + aoff1);
    uint2 Al0 = *(const uint2*)(Abase + APLANE + aoff0);
    uint2 Al1 = *(const uint2*)(Abase + APLANE + aoff1);
    #pragma unroll
    for (int j = 0; j < 4; ++j) {
        uint2 Bh = *(const uint2*)(Whi + bbase + j * (8 * WS));
        uint2 Bl = *(const uint2*)(Wlo + bbase + j * (8 * WS));
        mma16816(acc[j], Ah0.x, Ah1.x, Ah0.y, Ah1.y, Bh.x, Bh.y);
        mma16816(acc[j], Ah0.x, Ah1.x, Ah0.y, Ah1.y, Bl.x, Bl.y);
        mma16816(acc[j], Al0.x, Al1.x, Al0.y, Al1.y, Bh.x, Bh.y);
    }
}

// K-split reduction + bias + tanh + store to h (dest).
__device__ __forceinline__ void epilogue(float acc[4][4], float* red,
                                         int wid, int lane, int rread,
                                         float ba, float bb,
                                         size_t o0, size_t o1,
                                         float* __restrict__ dest) {
    float* st = red + wid * REDSTRIDE + lane * 20;
    #pragma unroll
    for (int j = 0; j < 4; ++j)
        *(float4*)(st + j * 4) =
            make_float4(acc[j][0], acc[j][1], acc[j][2], acc[j][3]);
    __syncthreads();
    float4 s = *(float4*)(red + rread);
    #pragma unroll
    for (int k = 1; k < 4; ++k) {
        float4 q = *(float4*)(red + rread + k * 2 * REDSTRIDE);
        s.x += q.x; s.y += q.y; s.z += q.z; s.w += q.w;
    }
    *(float2*)(dest + o0) = make_float2(tanhf(s.x + ba), tanhf(s.y + bb));
    *(float2*)(dest + o1) = make_float2(tanhf(s.z + ba), tanhf(s.w + bb));
    __syncthreads();
}

extern __shared__ u32 smem_u[];

__global__ void __launch_bounds__(BLOCKT, 1) rnn_persistent_kernel(
    const int*   __restrict__ x,
    const float* __restrict__ emb,
    const float* __restrict__ W_ih0, const float* __restrict__ b_ih0,
    const float* __restrict__ W_hh0, const float* __restrict__ b_hh0,
    const float* __restrict__ W_ih1, const float* __restrict__ b_ih1,
    const float* __restrict__ W_hh1, const float* __restrict__ b_hh1,
    const float* __restrict__ W_fc,  const float* __restrict__ b_fc,
    float* __restrict__ out)
{
    u32*   Whi = smem_u;                 // [32 cols][WS] packed fp16-hi kpairs
    u32*   Wlo = smem_u + 32 * WS;       // lo plane
    u32*   Ab  = smem_u + 64 * WS;       // [2 buf][2 plane][32][SA]
    float* red = (float*)Ab;             // epilogue scratch (aliases A)

    const int tid  = threadIdx.x;
    const int cta  = blockIdx.x;
    const int grp  = cta >> 4;
    const int row0 = grp * 32;
    const int col0 = (cta & 15) * 32;

    // ---- weight slice -> SMEM as fp16 hi/lo, k-pair-permuted ------------
    {
        const int c  = tid & 31;
        const int pp = tid >> 5;
        for (int pb = 0; pb < 800; pb += 8) {
            int kp = pb + pp;
            int k  = kp * 2;
            const float* src; int kr;
            if      (k < 64)   { src = W_ih0; kr = k; }
            else if (k < 576)  { src = W_hh0; kr = k - 64; }
            else if (k < 1088) { src = W_ih1; kr = k - 576; }
            else               { src = W_hh1; kr = k - 1088; }
            float w0 = src[(size_t)kr * HSn + col0 + c];
            float w1 = src[(size_t)(kr + 1) * HSn + col0 + c];
            int p   = kp & 7;
            int pos = (kp >> 3) * 8 + ((p < 4) ? 2 * p : 2 * p - 7);
            u32 hi, lo;
            split2(w0, w1, hi, lo);
            Whi[c * WS + pos] = hi;
            Wlo[c * WS + pos] = lo;
        }
    }
    __syncthreads();

    // ---- per-thread constants -------------------------------------------
    const int wid  = tid >> 5;
    const int lane = tid & 31;
    const int mh   = wid & 1;            // M-half (16 rows)
    const int ks   = wid >> 1;           // K-split quarter
    const int g    = lane >> 2;
    const int kt   = lane & 3;

    // A fragment offsets (chunk-local, buffer base added per chunk)
    const int aoff0 = (mh * 16 + g) * SA + ks * 8 + 2 * kt;
    const int aoff1 = aoff0 + 8 * SA;
    // B fragment column/lane part; chunk adds (lb + c*4)*8
    const int bcol  = g * WS + 2 * kt + ks * 8;

    // loader mapping
    const int ty  = tid >> 4;            // local rows ty, ty+16
    const int lt  = tid & 15;            // k-slice: k = 4*lt .. 4*lt+3
    const int ak4 = lt * 4;
    const int p0i = (2 * lt) & 7, p1i = (2 * lt + 1) & 7;
    const int pos0 = (lt >> 2) * 8 + ((p0i < 4) ? 2 * p0i : 2 * p0i - 7);
    const int pos1 = (lt >> 2) * 8 + ((p1i < 4) ? 2 * p1i : 2 * p1i - 7);
    const int r0g_ld = row0 + ty, r1g_ld = row0 + ty + 16;

    // epilogue mapping
    const int mh_r = tid >> 7;
    const int jr   = (tid >> 5) & 3;
    const int lr_  = tid & 31;
    const int gr   = lr_ >> 2, ktr = lr_ & 3;
    const int rread = mh_r * REDSTRIDE + lr_ * 20 + jr * 4;
    const int er0 = row0 + mh_r * 16 + gr;
    const int ec0 = col0 + jr * 8 + 2 * ktr;
    const size_t o0 = (size_t)er0 * HSn + ec0;
    const size_t o1 = (size_t)(er0 + 8) * HSn + ec0;
    const float l0ba = b_ih0[ec0] + b_hh0[ec0];
    const float l0bb = b_ih0[ec0 + 1] + b_hh0[ec0 + 1];
    const float l1ba = b_ih1[ec0] + b_hh1[ec0];
    const float l1bb = b_ih1[ec0 + 1] + b_hh1[ec0 + 1];

    for (int t = 0; t < Tn; ++t) {
        const float* h0_prev = g_h0[(t & 1) ^ 1];
        float*       h0_cur  = g_h0[t & 1];
        const float* h1_prev = g_outs + (size_t)(t - 1) * Bn * HSn;  // t>0
        float*       h1_cur  = g_outs + (size_t)t * Bn * HSn;

        // ===== layer 0: h0 = tanh([emb | h0_prev] @ [Wih0;Whh0] + b) =====
        {
            const int nch = (t == 0) ? 1 : 9;
            float4 p0, p1;
            {
                int xi0 = x[r0g_ld * Tn + t];
                int xi1 = x[r1g_ld * Tn + t];
                p0 = *(const float4*)&emb[xi0 * EMBn + ak4];
                p1 = *(const float4*)&emb[xi1 * EMBn + ak4];
                storeA(Ab, ty, pos0, pos1, p0);
                storeA(Ab, ty + 16, pos0, pos1, p1);
            }
            if (nch > 1) {
                p0 = __ldcg((const float4*)&h0_prev[(size_t)r0g_ld * HSn + ak4]);
                p1 = __ldcg((const float4*)&h0_prev[(size_t)r1g_ld * HSn + ak4]);
            }
            __syncthreads();

            float acc[4][4];
            #pragma unroll
            for (int j = 0; j < 4; ++j)
                #pragma unroll
                for (int r = 0; r < 4; ++r) acc[j][r] = 0.f;

            #pragma unroll 1
            for (int c = 0; c < nch; ++c) {
                if (c + 1 < nch) {
                    u32* An = Ab + ((c + 1) & 1) * ABUFSZ;
                    storeA(An, ty, pos0, pos1, p0);
                    storeA(An, ty + 16, pos0, pos1, p1);
                }
                if (c + 2 < nch) {
                    int kb = (c + 1) * KC;
                    p0 = __ldcg((const float4*)&h0_prev[(size_t)r0g_ld * HSn + kb + ak4]);
                    p1 = __ldcg((const float4*)&h0_prev[(size_t)r1g_ld * HSn + kb + ak4]);
                }
                chunk_mma(Ab + (c & 1) * ABUFSZ, Whi, Wlo,
                          aoff0, aoff1, bcol + c * 32, acc);
                __syncthreads();
            }
            epilogue(acc, red, wid, lane, rread, l0ba, l0bb, o0, o1, h0_cur);
        }
        group_sync(grp);

        // ===== layer 1: h1 = tanh([h0_cur | h1_prev] @ [Wih1;Whh1] + b) ==
        {
            const int nch = (t == 0) ? 8 : 16;
            float4 p0, p1;
            p0 = __ldcg((const float4*)&h0_cur[(size_t)r0g_ld * HSn + ak4]);
            p1 = __ldcg((const float4*)&h0_cur[(size_t)r1g_ld * HSn + ak4]);
            storeA(Ab, ty, pos0, pos1, p0);
            storeA(Ab, ty + 16, pos0, pos1, p1);
            p0 = __ldcg((const float4*)&h0_cur[(size_t)r0g_ld * HSn + KC + ak4]);
            p1 = __ldcg((const float4*)&h0_cur[(size_t)r1g_ld * HSn + KC + ak4]);
            __syncthreads();

            float acc[4][4];
            #pragma unroll
            for (int j = 0; j < 4; ++j)
                #pragma unroll
                for (int r = 0; r < 4; ++r) acc[j][r] = 0.f;

            #pragma unroll 1
            for (int c = 0; c < nch; ++c) {
                if (c + 1 < nch) {
                    u32* An = Ab + ((c + 1) & 1) * ABUFSZ;
                    storeA(An, ty, pos0, pos1, p0);
                    storeA(An, ty + 16, pos0, pos1, p1);
                }
                if (c + 2 < nch) {
                    const int ci = c + 2;
                    const float* hs = (ci < 8) ? h0_cur : h1_prev;
                    const int kb = (ci < 8) ? ci * KC : (ci - 8) * KC;
                    p0 = __ldcg((const float4*)&hs[(size_t)r0g_ld * HSn + kb + ak4]);
                    p1 = __ldcg((const float4*)&hs[(size_t)r1g_ld * HSn + kb + ak4]);
                }
                chunk_mma(Ab + (c & 1) * ABUFSZ, Whi, Wlo,
                          aoff0, aoff1, bcol + 288 + c * 32, acc);
                __syncthreads();
            }
            epilogue(acc, red, wid, lane, rread, l1ba, l1bb, o0, o1, h1_cur);
        }
        // no barrier: next step's post-L0 group_sync transitively orders h1.
    }

    grid_sync_all();

    // ===== final FC (fp32 path, unchanged): logits = h1 @ W_fc + b_fc ====
    float* smf = (float*)smem_u;
    float* fcA = smf;                   // [64][FCPAD]
    float* fcB = smf + 64 * FCPAD;      // [128][FCPAD]

    const int lkk = tid & 31;
    const int lr  = tid >> 5;
    const int fty = tid >> 5;
    const int ftx = tid & 31;
    const int fj  = tid & 127;
    const int fkk = tid >> 7;
    const int NTILES = (Bn * Tn) / 64;

    for (int tile = cta; tile < NTILES; tile += GRID) {
        const int m0 = tile * 64;
        float acc[8][4];
        #pragma unroll
        for (int ii = 0; ii < 8; ++ii)
            #pragma unroll
            for (int jj = 0; jj < 4; ++jj) acc[ii][jj] = 0.f;

        #pragma unroll 1
        for (int k0 = 0; k0 < HSn; k0 += 32) {
            __syncthreads();
            #pragma unroll
            for (int rr = lr; rr < 64; rr += 8)
                fcA[rr * FCPAD + lkk] =
                    g_outs[(size_t)(m0 + rr) * HSn + k0 + lkk];
            #pragma unroll
            for (int kx = fkk; kx < 32; kx += 2)
                fcB[fj * FCPAD + kx] = W_fc[(size_t)(k0 + kx) * VSn + fj];
            __syncthreads();
            #pragma unroll
            for (int k4 = 0; k4 < 32; k4 += 4) {
                float4 bv[4];
                #pragma unroll
                for (int jj = 0; jj < 4; ++jj)
                    bv[jj] = *(const float4*)&fcB[(ftx + 32 * jj) * FCPAD + k4];
                #pragma unroll
                for (int ii = 0; ii < 8; ++ii) {
                    float4 av = *(const float4*)&fcA[(fty + 8 * ii) * FCPAD + k4];
                    #pragma unroll
                    for (int jj = 0; jj < 4; ++jj) {
                        acc[ii][jj] += av.x * bv[jj].x;
                        acc[ii][jj] += av.y * bv[jj].y;
                        acc[ii][jj] += av.z * bv[jj].z;
                        acc[ii][jj] += av.w * bv[jj].w;
                    }
                }
            }
        }
        #pragma unroll
        for (int ii = 0; ii < 8; ++ii) {
            const int m  = m0 + fty + 8 * ii;
            const int tt = m >> 8;
            const int bb = m & 255;
            float* op = out + ((size_t)bb * Tn + tt) * VSn;
            #pragma unroll
            for (int jj = 0; jj < 4; ++jj) {
                const int c = ftx + 32 * jj;
                op[c] = acc[ii][jj] + b_fc[c];
            }
        }
        __syncthreads();
    }
}

extern "C" void kernel_launch(void* const* d_in, const int* in_sizes, int n_in,
                              void* d_out, int out_size) {
    const int*   x      = (const int*)  d_in[0];
    const float* emb    = (const float*)d_in[1];
    const float* W_ih0  = (const float*)d_in[2];
    const float* b_ih0  = (const float*)d_in[3];
    const float* W_hh0  = (const float*)d_in[4];
    const float* b_hh0  = (const float*)d_in[5];
    const float* W_ih1  = (const float*)d_in[6];
    const float* b_ih1  = (const float*)d_in[7];
    const float* W_hh1  = (const float*)d_in[8];
    const float* b_hh1  = (const float*)d_in[9];
    const float* W_fc   = (const float*)d_in[10];
    const float* b_fc   = (const float*)d_in[11];
    float* out = (float*)d_out;

    cudaFuncSetAttribute(rnn_persistent_kernel,
                         cudaFuncAttributeMaxDynamicSharedMemorySize, SMEM_BYTES);

    rnn_persistent_kernel<<<GRID, BLOCKT, SMEM_BYTES>>>(
        x, emb, W_ih0, b_ih0, W_hh0, b_hh0,
        W_ih1, b_ih1, W_hh1, b_hh1, W_fc, b_fc, out);
}

// round 8
// speedup vs baseline: 2.1819x; 1.0979x over previous
#include <cuda_runtime.h>
#include <cuda_fp16.h>

// Problem sizes
#define Bn   256
#define Tn   512
#define EMBn 64
#define HSn  512
#define VSn  128

// 8 row-groups (32 batch rows) x 16 col-tiles (32 hidden cols) = 128 CTAs
#define GRID   128
#define NGROUP 8
#define GSIZE  16
#define BLOCKT 256
#define KC     64            // K-chunk = 4 k16 blocks (one per K-split warp)
#define WS     808           // W plane row stride in u32 kpairs (800 + pad)
#define HPS    512           // packed-h row stride in u32 (256 kpairs * 2)
#define REDSTRIDE 640        // epilogue reduction per-warp float stride
#define FCPAD  36

#define SMEM_U32   (2 * 32 * WS + 5120)   // weights hi/lo + reduction scratch
#define SMEM_BYTES (SMEM_U32 * 4)         // 227,328 B

typedef unsigned int u32;

// -------- persistent device state ----------------------------------------
// h stored packed: per kpair slot (fragment-permuted), uint2 = (fp16x2 hi, fp16x2 lo)
__device__ u32 g_h0p[2][Bn * HPS];                  // ping-pong h0
__device__ u32 g_outsp[(size_t)Tn * Bn * HPS];      // h1 history [t][b][..]
__device__ u32 g_embp[VSn * EMBn];                  // packed embedding (32 kpair*2)
struct PadCnt { unsigned v; unsigned pad[31]; };
__device__ PadCnt g_gcnt[NGROUP];
__device__ volatile unsigned g_gphase[NGROUP * 32];
__device__ unsigned g_allcnt;
__device__ volatile unsigned g_allphase;

__device__ __forceinline__ void group_sync(int g) {
    __threadfence();
    __syncthreads();
    if (threadIdx.x == 0) {
        unsigned ph = g_gphase[g * 32];
        if (atomicAdd(&g_gcnt[g].v, 1u) == GSIZE - 1u) {
            g_gcnt[g].v = 0u;
            __threadfence();
            g_gphase[g * 32] = ph + 1u;
        } else {
            while (g_gphase[g * 32] == ph) { }
        }
    }
    __syncthreads();
}

__device__ __forceinline__ void grid_sync_all() {
    __threadfence();
    __syncthreads();
    if (threadIdx.x == 0) {
        unsigned ph = g_allphase;
        if (atomicAdd(&g_allcnt, 1u) == GRID - 1u) {
            g_allcnt = 0u;
            __threadfence();
            g_allphase = ph + 1u;
        } else {
            while (g_allphase == ph) { }
        }
    }
    __syncthreads();
}

// -------- fp16 split + mma helpers ---------------------------------------
__device__ __forceinline__ void split2(float x, float y, u32& hi, u32& lo) {
    __half hx = __float2half_rn(x), hy = __float2half_rn(y);
    __half lx = __float2half_rn(x - __half2float(hx));
    __half ly = __float2half_rn(y - __half2float(hy));
    __half2 h = __halves2half2(hx, hy), l = __halves2half2(lx, ly);
    hi = *(u32*)&h; lo = *(u32*)&l;
}

// global kpair index -> permuted slot (fragment order within each 8-kpair group)
__device__ __forceinline__ int permslot(int kp) {
    int p = kp & 7;
    return (kp & ~7) + ((p < 4) ? 2 * p : 2 * p - 7);
}

__device__ __forceinline__ void mma16816(float c[4],
                                         u32 a0, u32 a1, u32 a2, u32 a3,
                                         u32 b0, u32 b1) {
    asm volatile(
        "mma.sync.aligned.m16n8k16.row.col.f32.f16.f16.f32 "
        "{%0,%1,%2,%3}, {%4,%5,%6,%7}, {%8,%9}, {%0,%1,%2,%3};"
        : "+f"(c[0]), "+f"(c[1]), "+f"(c[2]), "+f"(c[3])
        : "r"(a0), "r"(a1), "r"(a2), "r"(a3), "r"(b0), "r"(b1));
}

// One KC chunk (this warp's k16 block): A fragments already in regs as packed
// uint4 {hi_kt, lo_kt, hi_kt+4, lo_kt+4}; 4 n-blocks x 3 split products.
__device__ __forceinline__ void chunk_mma_p(uint4 u0, uint4 u1,
                                            const u32* __restrict__ Whi,
                                            const u32* __restrict__ Wlo,
                                            int bbase, float acc[4][4]) {
    #pragma unroll
    for (int j = 0; j < 4; ++j) {
        uint2 Bh = *(const uint2*)(Whi + bbase + j * (8 * WS));
        uint2 Bl = *(const uint2*)(Wlo + bbase + j * (8 * WS));
        mma16816(acc[j], u0.x, u1.x, u0.z, u1.z, Bh.x, Bh.y);  // Ah*Bh
        mma16816(acc[j], u0.x, u1.x, u0.z, u1.z, Bl.x, Bl.y);  // Ah*Bl
        mma16816(acc[j], u0.y, u1.y, u0.w, u1.w, Bh.x, Bh.y);  // Al*Bh
    }
}

// K-split reduction + bias + tanh + packed (hi,lo) store.
__device__ __forceinline__ void epilogue_p(float acc[4][4], float* red,
                                           int wid, int lane, int rread,
                                           float ba, float bb,
                                           size_t po0, size_t po1,
                                           u32* __restrict__ destp) {
    float* st = red + wid * REDSTRIDE + lane * 20;
    #pragma unroll
    for (int j = 0; j < 4; ++j)
        *(float4*)(st + j * 4) =
            make_float4(acc[j][0], acc[j][1], acc[j][2], acc[j][3]);
    __syncthreads();
    float4 s = *(float4*)(red + rread);
    #pragma unroll
    for (int k = 1; k < 4; ++k) {
        float4 q = *(float4*)(red + rread + k * 2 * REDSTRIDE);
        s.x += q.x; s.y += q.y; s.z += q.z; s.w += q.w;
    }
    u32 hi, lo;
    split2(tanhf(s.x + ba), tanhf(s.y + bb), hi, lo);
    *(uint2*)(destp + po0) = make_uint2(hi, lo);
    split2(tanhf(s.z + ba), tanhf(s.w + bb), hi, lo);
    *(uint2*)(destp + po1) = make_uint2(hi, lo);
    __syncthreads();
}

extern __shared__ u32 smem_u[];

__global__ void __launch_bounds__(BLOCKT, 1) rnn_persistent_kernel(
    const int*   __restrict__ x,
    const float* __restrict__ emb,
    const float* __restrict__ W_ih0, const float* __restrict__ b_ih0,
    const float* __restrict__ W_hh0, const float* __restrict__ b_hh0,
    const float* __restrict__ W_ih1, const float* __restrict__ b_ih1,
    const float* __restrict__ W_hh1, const float* __restrict__ b_hh1,
    const float* __restrict__ W_fc,  const float* __restrict__ b_fc,
    float* __restrict__ out)
{
    u32*   Whi = smem_u;                 // [32 cols][WS] fp16-hi kpairs
    u32*   Wlo = smem_u + 32 * WS;       // lo plane
    float* red = (float*)(smem_u + 64 * WS);   // epilogue scratch (5120 f)

    const int tid  = threadIdx.x;
    const int cta  = blockIdx.x;
    const int grp  = cta >> 4;
    const int row0 = grp * 32;
    const int col0 = (cta & 15) * 32;

    // ---- weight slice -> SMEM as fp16 hi/lo, fragment-permuted ----------
    {
        const int c  = tid & 31;
        const int pp = tid >> 5;
        for (int pb = 0; pb < 800; pb += 8) {
            int kp = pb + pp;
            int k  = kp * 2;
            const float* src; int kr;
            if      (k < 64)   { src = W_ih0; kr = k; }
            else if (k < 576)  { src = W_hh0; kr = k - 64; }
            else if (k < 1088) { src = W_ih1; kr = k - 576; }
            else               { src = W_hh1; kr = k - 1088; }
            float w0 = src[(size_t)kr * HSn + col0 + c];
            float w1 = src[(size_t)(kr + 1) * HSn + col0 + c];
            u32 hi, lo;
            split2(w0, w1, hi, lo);
            int pos = permslot(kp);
            Whi[c * WS + pos] = hi;
            Wlo[c * WS + pos] = lo;
        }
    }

    // ---- packed embedding precompute: CTA i owns vocab row i -------------
    if (tid < 32) {
        float w0 = emb[cta * EMBn + 2 * tid];
        float w1 = emb[cta * EMBn + 2 * tid + 1];
        u32 hi, lo;
        split2(w0, w1, hi, lo);
        int slot = permslot(tid);
        g_embp[cta * EMBn + slot * 2]     = hi;
        g_embp[cta * EMBn + slot * 2 + 1] = lo;
    }
    grid_sync_all();

    // ---- per-thread constants -------------------------------------------
    const int wid  = tid >> 5;
    const int lane = tid & 31;
    const int mh   = wid & 1;            // M-half (16 rows)
    const int ks   = wid >> 1;           // K-split quarter
    const int g    = lane >> 2;
    const int kt   = lane & 3;

    const int fr0  = row0 + mh * 16 + g; // absolute batch rows of A fragment
    const int fr1  = fr0 + 8;
    const int uoff = (ks * 8 + 2 * kt) * 2;   // u32 offset of fragment in a chunk
    const int bcol = g * WS + 2 * kt + ks * 8;

    // epilogue mapping (identical to validated R7 layout)
    const int mh_r = tid >> 7;
    const int jr   = (tid >> 5) & 3;
    const int lr_  = tid & 31;
    const int gr   = lr_ >> 2, ktr = lr_ & 3;
    const int rread = mh_r * REDSTRIDE + lr_ * 20 + jr * 4;
    const int er0 = row0 + mh_r * 16 + gr;
    const int ec0 = col0 + jr * 8 + 2 * ktr;
    const int eslot = permslot(ec0 >> 1);
    const size_t po0 = (size_t)er0 * HPS + eslot * 2;
    const size_t po1 = (size_t)(er0 + 8) * HPS + eslot * 2;
    const float l0ba = b_ih0[ec0] + b_hh0[ec0];
    const float l0bb = b_ih0[ec0 + 1] + b_hh0[ec0 + 1];
    const float l1ba = b_ih1[ec0] + b_hh1[ec0];
    const float l1bb = b_ih1[ec0 + 1] + b_hh1[ec0 + 1];

    for (int t = 0; t < Tn; ++t) {
        const u32* h0_prev_p = g_h0p[(t & 1) ^ 1];
        u32*       h0_cur_p  = g_h0p[t & 1];
        const u32* h1_prev_p = g_outsp + ((long)t - 1) * (long)(Bn * HPS);
        u32*       h1_cur_p  = g_outsp + (size_t)t * (Bn * HPS);

        // ===== layer 0: h0 = tanh([emb | h0_prev] @ [Wih0;Whh0] + b) =====
        {
            int xi0 = x[fr0 * Tn + t];
            int xi1 = x[fr1 * Tn + t];
            uint4 e0 = __ldcg((const uint4*)(g_embp + xi0 * EMBn + uoff));
            uint4 e1 = __ldcg((const uint4*)(g_embp + xi1 * EMBn + uoff));

            float acc[4][4];
            #pragma unroll
            for (int j = 0; j < 4; ++j)
                #pragma unroll
                for (int r = 0; r < 4; ++r) acc[j][r] = 0.f;

            if (t > 0) {
                const u32* hp0 = h0_prev_p + (size_t)fr0 * HPS + uoff;
                const u32* hp1 = h0_prev_p + (size_t)fr1 * HPS + uoff;
                uint4 c0 = __ldcg((const uint4*)hp0);
                uint4 c1 = __ldcg((const uint4*)hp1);
                uint4 n0 = __ldcg((const uint4*)(hp0 + 64));
                uint4 n1 = __ldcg((const uint4*)(hp1 + 64));
                chunk_mma_p(e0, e1, Whi, Wlo, bcol, acc);      // emb chunk
                #pragma unroll 1
                for (int c = 1; c <= 8; ++c) {
                    uint4 t0 = c0, t1 = c1;
                    if (c + 2 <= 8) {
                        t0 = __ldcg((const uint4*)(hp0 + (c + 1) * 64));
                        t1 = __ldcg((const uint4*)(hp1 + (c + 1) * 64));
                    }
                    chunk_mma_p(c0, c1, Whi, Wlo, bcol + c * 32, acc);
                    c0 = n0; c1 = n1; n0 = t0; n1 = t1;
                }
            } else {
                chunk_mma_p(e0, e1, Whi, Wlo, bcol, acc);
            }
            epilogue_p(acc, red, wid, lane, rread, l0ba, l0bb, po0, po1,
                       h0_cur_p);
        }
        group_sync(grp);

        // ===== layer 1: h1 = tanh([h0_cur | h1_prev] @ [Wih1;Whh1] + b) ==
        {
            const u32* h0c0 = h0_cur_p + (size_t)fr0 * HPS + uoff;
            const u32* h0c1 = h0_cur_p + (size_t)fr1 * HPS + uoff;
            const u32* h1p0 = h1_prev_p + (size_t)fr0 * HPS + uoff;
            const u32* h1p1 = h1_prev_p + (size_t)fr1 * HPS + uoff;
            const int nch = (t == 0) ? 8 : 16;

            float acc[4][4];
            #pragma unroll
            for (int j = 0; j < 4; ++j)
                #pragma unroll
                for (int r = 0; r < 4; ++r) acc[j][r] = 0.f;

            uint4 c0 = __ldcg((const uint4*)h0c0);
            uint4 c1 = __ldcg((const uint4*)h0c1);
            uint4 n0 = __ldcg((const uint4*)(h0c0 + 64));
            uint4 n1 = __ldcg((const uint4*)(h0c1 + 64));
            #pragma unroll 1
            for (int c = 0; c < nch; ++c) {
                uint4 t0 = c0, t1 = c1;
                if (c + 2 < nch) {
                    const int ci = c + 2;
                    const u32* a0 = (ci < 8) ? (h0c0 + ci * 64)
                                             : (h1p0 + (ci - 8) * 64);
                    const u32* a1 = (ci < 8) ? (h0c1 + ci * 64)
                                             : (h1p1 + (ci - 8) * 64);
                    t0 = __ldcg((const uint4*)a0);
                    t1 = __ldcg((const uint4*)a1);
                }
                chunk_mma_p(c0, c1, Whi, Wlo, bcol + 288 + c * 32, acc);
                c0 = n0; c1 = n1; n0 = t0; n1 = t1;
            }
            epilogue_p(acc, red, wid, lane, rread, l1ba, l1bb, po0, po1,
                       h1_cur_p);
        }
        // no barrier: next step's post-L0 group_sync transitively orders h1.
    }

    grid_sync_all();

    // ===== final FC (fp32): logits = h1 @ W_fc + b_fc ====================
    float* smf = (float*)smem_u;
    float* fcA = smf;                   // [64][FCPAD]
    float* fcB = smf + 64 * FCPAD;      // [128][FCPAD]

    const int fs   = tid & 15;          // slot within 16-slot chunk section
    const int frb  = tid >> 4;          // 0..15 row base
    const int prel = (fs & 8) + ((fs & 1) ? ((fs & 7) >> 1) + 4
                                          : ((fs & 7) >> 1));   // unpermuted kpair
    const int fty = tid >> 5;
    const int ftx = tid & 31;
    const int fj  = tid & 127;
    const int fkk = tid >> 7;
    const int NTILES = (Bn * Tn) / 64;

    for (int tile = cta; tile < NTILES; tile += GRID) {
        const int m0 = tile * 64;
        float acc[8][4];
        #pragma unroll
        for (int ii = 0; ii < 8; ++ii)
            #pragma unroll
            for (int jj = 0; jj < 4; ++jj) acc[ii][jj] = 0.f;

        #pragma unroll 1
        for (int k0 = 0; k0 < HSn; k0 += 32) {
            __syncthreads();
            #pragma unroll
            for (int rr = frb; rr < 64; rr += 16) {
                uint2 v = __ldcg((const uint2*)(g_outsp +
                           (size_t)(m0 + rr) * HPS + k0 + 2 * fs));
                __half2 h2 = *(__half2*)&v.x;
                __half2 l2 = *(__half2*)&v.y;
                fcA[rr * FCPAD + 2 * prel]     = __low2float(h2) + __low2float(l2);
                fcA[rr * FCPAD + 2 * prel + 1] = __high2float(h2) + __high2float(l2);
            }
            #pragma unroll
            for (int kx = fkk; kx < 32; kx += 2)
                fcB[fj * FCPAD + kx] = W_fc[(size_t)(k0 + kx) * VSn + fj];
            __syncthreads();
            #pragma unroll
            for (int k4 = 0; k4 < 32; k4 += 4) {
                float4 bv[4];
                #pragma unroll
                for (int jj = 0; jj < 4; ++jj)
                    bv[jj] = *(const float4*)&fcB[(ftx + 32 * jj) * FCPAD + k4];
                #pragma unroll
                for (int ii = 0; ii < 8; ++ii) {
                    float4 av = *(const float4*)&fcA[(fty + 8 * ii) * FCPAD + k4];
                    #pragma unroll
                    for (int jj = 0; jj < 4; ++jj) {
                        acc[ii][jj] += av.x * bv[jj].x;
                        acc[ii][jj] += av.y * bv[jj].y;
                        acc[ii][jj] += av.z * bv[jj].z;
                        acc[ii][jj] += av.w * bv[jj].w;
                    }
                }
            }
        }
        #pragma unroll
        for (int ii = 0; ii < 8; ++ii) {
            const int m  = m0 + fty + 8 * ii;
            const int tt = m >> 8;
            const int bb = m & 255;
            float* op = out + ((size_t)bb * Tn + tt) * VSn;
            #pragma unroll
            for (int jj = 0; jj < 4; ++jj) {
                const int c = ftx + 32 * jj;
                op[c] = acc[ii][jj] + b_fc[c];
            }
        }
        __syncthreads();
    }
}

extern "C" void kernel_launch(void* const* d_in, const int* in_sizes, int n_in,
                              void* d_out, int out_size) {
    const int*   x      = (const int*)  d_in[0];
    const float* emb    = (const float*)d_in[1];
    const float* W_ih0  = (const float*)d_in[2];
    const float* b_ih0  = (const float*)d_in[3];
    const float* W_hh0  = (const float*)d_in[4];
    const float* b_hh0  = (const float*)d_in[5];
    const float* W_ih1  = (const float*)d_in[6];
    const float* b_ih1  = (const float*)d_in[7];
    const float* W_hh1  = (const float*)d_in[8];
    const float* b_hh1  = (const float*)d_in[9];
    const float* W_fc   = (const float*)d_in[10];
    const float* b_fc   = (const float*)d_in[11];
    float* out = (float*)d_out;

    cudaFuncSetAttribute(rnn_persistent_kernel,
                         cudaFuncAttributeMaxDynamicSharedMemorySize, SMEM_BYTES);

    rnn_persistent_kernel<<<GRID, BLOCKT, SMEM_BYTES>>>(
        x, emb, W_ih0, b_ih0, W_hh0, b_hh0,
        W_ih1, b_ih1, W_hh1, b_hh1, W_fc, b_fc, out);
}

// round 9
// speedup vs baseline: 2.3085x; 1.0580x over previous
#include <cuda_runtime.h>
#include <cuda_fp16.h>

// Problem sizes
#define Bn   256
#define Tn   512
#define EMBn 64
#define HSn  512
#define VSn  128

// 8 row-groups (32 batch rows) x 16 col-tiles (32 hidden cols) = 128 CTAs
#define GRID   128
#define NGROUP 8
#define GSIZE  16
#define BLOCKT 512
#define WS     808           // W plane row stride in u32 kpairs (800 + pad)
#define HPS    512           // packed-h row stride in u32 (256 kpairs * 2)
#define RS     296           // recurrence reduction stride (floats per src lane-row blk)
#define WS2    264           // FC B plane row stride (256 kpairs + pad)
#define RS2    672           // FC reduction stride (32*21)

#define SMEM_U32   (2 * 32 * WS + 5120)   // weights hi/lo + reduction scratch
#define SMEM_BYTES (SMEM_U32 * 4)         // 227,328 B  (FC reuses same region)

typedef unsigned int u32;

// -------- persistent device state ----------------------------------------
__device__ u32 g_h0p[2][Bn * HPS];                  // ping-pong packed h0
__device__ u32 g_outsp[(size_t)Tn * Bn * HPS];      // packed h1 history
__device__ u32 g_embp[VSn * EMBn];                  // packed embedding
struct PadCnt { unsigned v; unsigned pad[31]; };
__device__ PadCnt g_gcnt[NGROUP];
__device__ volatile unsigned g_gphase[NGROUP * 32];
__device__ unsigned g_allcnt;
__device__ volatile unsigned g_allphase;

__device__ __forceinline__ void group_sync(int g) {
    __threadfence();
    __syncthreads();
    if (threadIdx.x == 0) {
        unsigned ph = g_gphase[g * 32];
        if (atomicAdd(&g_gcnt[g].v, 1u) == GSIZE - 1u) {
            g_gcnt[g].v = 0u;
            __threadfence();
            g_gphase[g * 32] = ph + 1u;
        } else {
            while (g_gphase[g * 32] == ph) { }
        }
    }
    __syncthreads();
}

__device__ __forceinline__ void grid_sync_all() {
    __threadfence();
    __syncthreads();
    if (threadIdx.x == 0) {
        unsigned ph = g_allphase;
        if (atomicAdd(&g_allcnt, 1u) == GRID - 1u) {
            g_allcnt = 0u;
            __threadfence();
            g_allphase = ph + 1u;
        } else {
            while (g_allphase == ph) { }
        }
    }
    __syncthreads();
}

// -------- fp16 split + mma helpers ---------------------------------------
__device__ __forceinline__ void split2(float x, float y, u32& hi, u32& lo) {
    __half hx = __float2half_rn(x), hy = __float2half_rn(y);
    __half lx = __float2half_rn(x - __half2float(hx));
    __half ly = __float2half_rn(y - __half2float(hy));
    __half2 h = __halves2half2(hx, hy), l = __halves2half2(lx, ly);
    hi = *(u32*)&h; lo = *(u32*)&l;
}

__device__ __forceinline__ int permslot(int kp) {
    int p = kp & 7;
    return (kp & ~7) + ((p < 4) ? 2 * p : 2 * p - 7);
}

__device__ __forceinline__ void mma16816(float c[4],
                                         u32 a0, u32 a1, u32 a2, u32 a3,
                                         u32 b0, u32 b1) {
    asm volatile(
        "mma.sync.aligned.m16n8k16.row.col.f32.f16.f16.f32 "
        "{%0,%1,%2,%3}, {%4,%5,%6,%7}, {%8,%9}, {%0,%1,%2,%3};"
        : "+f"(c[0]), "+f"(c[1]), "+f"(c[2]), "+f"(c[3])
        : "r"(a0), "r"(a1), "r"(a2), "r"(a3), "r"(b0), "r"(b1));
}

// One KC chunk, this warp's k16 block and its 2 n-blocks (3 split products).
__device__ __forceinline__ void chunk_mma2(uint4 u0, uint4 u1,
                                           const u32* __restrict__ Whi,
                                           const u32* __restrict__ Wlo,
                                           int bbase, float acc[2][4]) {
    #pragma unroll
    for (int jl = 0; jl < 2; ++jl) {
        uint2 Bh = *(const uint2*)(Whi + bbase + jl * (8 * WS));
        uint2 Bl = *(const uint2*)(Wlo + bbase + jl * (8 * WS));
        mma16816(acc[jl], u0.x, u1.x, u0.z, u1.z, Bh.x, Bh.y);  // Ah*Bh
        mma16816(acc[jl], u0.x, u1.x, u0.z, u1.z, Bl.x, Bl.y);  // Ah*Bl
        mma16816(acc[jl], u0.y, u1.y, u0.w, u1.w, Bh.x, Bh.y);  // Al*Bh
    }
}

// K-split reduction + bias + tanh + packed (hi,lo) store. One uint2 / thread.
__device__ __forceinline__ void epilogue2(float acc[2][4], float* red,
                                          int wid, int lane, int rbase,
                                          float ba, float bb,
                                          size_t po, u32* __restrict__ destp) {
    float* st = red + wid * RS + lane * 9;
    st[0] = acc[0][0]; st[1] = acc[0][1]; st[2] = acc[0][2]; st[3] = acc[0][3];
    st[4] = acc[1][0]; st[5] = acc[1][1]; st[6] = acc[1][2]; st[7] = acc[1][3];
    __syncthreads();
    float s0 = 0.f, s1 = 0.f;
    #pragma unroll
    for (int k = 0; k < 4; ++k) {
        const float* q = red + rbase + k * (4 * RS);
        s0 += q[0]; s1 += q[1];
    }
    u32 hi, lo;
    split2(tanhf(s0 + ba), tanhf(s1 + bb), hi, lo);
    *(uint2*)(destp + po) = make_uint2(hi, lo);
    __syncthreads();
}

extern __shared__ u32 smem_u[];

__global__ void __launch_bounds__(BLOCKT, 1) rnn_persistent_kernel(
    const int*   __restrict__ x,
    const float* __restrict__ emb,
    const float* __restrict__ W_ih0, const float* __restrict__ b_ih0,
    const float* __restrict__ W_hh0, const float* __restrict__ b_hh0,
    const float* __restrict__ W_ih1, const float* __restrict__ b_ih1,
    const float* __restrict__ W_hh1, const float* __restrict__ b_hh1,
    const float* __restrict__ W_fc,  const float* __restrict__ b_fc,
    float* __restrict__ out)
{
    u32*   Whi = smem_u;                       // [32 cols][WS]
    u32*   Wlo = smem_u + 32 * WS;
    float* red = (float*)(smem_u + 64 * WS);   // 5120 floats scratch

    const int tid  = threadIdx.x;
    const int cta  = blockIdx.x;
    const int grp  = cta >> 4;
    const int row0 = grp * 32;
    const int col0 = (cta & 15) * 32;

    // ---- weight slice -> SMEM as fp16 hi/lo, fragment-permuted ----------
    {
        const int c  = tid & 31;
        const int pp = tid >> 5;               // 0..15
        for (int pb = 0; pb < 800; pb += 16) {
            int kp = pb + pp;
            int k  = kp * 2;
            const float* src; int kr;
            if      (k < 64)   { src = W_ih0; kr = k; }
            else if (k < 576)  { src = W_hh0; kr = k - 64; }
            else if (k < 1088) { src = W_ih1; kr = k - 576; }
            else               { src = W_hh1; kr = k - 1088; }
            float w0 = src[(size_t)kr * HSn + col0 + c];
            float w1 = src[(size_t)(kr + 1) * HSn + col0 + c];
            u32 hi, lo;
            split2(w0, w1, hi, lo);
            int pos = permslot(kp);
            Whi[c * WS + pos] = hi;
            Wlo[c * WS + pos] = lo;
        }
    }

    // ---- packed embedding precompute: CTA i owns vocab row i -------------
    if (tid < 32) {
        float w0 = emb[cta * EMBn + 2 * tid];
        float w1 = emb[cta * EMBn + 2 * tid + 1];
        u32 hi, lo;
        split2(w0, w1, hi, lo);
        int slot = permslot(tid);
        g_embp[cta * EMBn + slot * 2]     = hi;
        g_embp[cta * EMBn + slot * 2 + 1] = lo;
    }
    grid_sync_all();

    // ---- warp decomposition: wid = mh + 2*nh + 4*ks ----------------------
    const int wid  = tid >> 5;
    const int lane = tid & 31;
    const int mh   = wid & 1;
    const int nh   = (wid >> 1) & 1;
    const int ks   = wid >> 2;            // 0..3 K-split
    const int g    = lane >> 2;
    const int kt   = lane & 3;

    const int fr0  = row0 + mh * 16 + g;
    const int fr1  = fr0 + 8;
    const int uoff = (ks * 8 + 2 * kt) * 2;
    const int bcol = (nh * 16 + g) * WS + 2 * kt + ks * 8;

    // epilogue read-side mapping: w -> (mh_r, jg, rh)
    const int mh_r = wid & 1;
    const int jg   = (wid >> 1) & 3;
    const int rh   = wid >> 3;
    const int gr   = lane >> 2, ktr = lane & 3;
    const int er   = row0 + mh_r * 16 + rh * 8 + gr;
    const int ec0  = col0 + jg * 8 + 2 * ktr;
    const size_t po = (size_t)er * HPS + permslot(ec0 >> 1) * 2;
    const int rbase = (mh_r + 2 * (jg >> 1)) * RS + (gr * 4 + ktr) * 9
                    + (jg & 1) * 4 + rh * 2;
    const float l0ba = b_ih0[ec0] + b_hh0[ec0];
    const float l0bb = b_ih0[ec0 + 1] + b_hh0[ec0 + 1];
    const float l1ba = b_ih1[ec0] + b_hh1[ec0];
    const float l1bb = b_ih1[ec0 + 1] + b_hh1[ec0 + 1];

    for (int t = 0; t < Tn; ++t) {
        const u32* h0_prev_p = g_h0p[(t & 1) ^ 1];
        u32*       h0_cur_p  = g_h0p[t & 1];
        const u32* h1_prev_p = g_outsp + ((long)t - 1) * (long)(Bn * HPS);
        u32*       h1_cur_p  = g_outsp + (size_t)t * (Bn * HPS);

        // ===== layer 0 ====================================================
        {
            int xi0 = x[fr0 * Tn + t];
            int xi1 = x[fr1 * Tn + t];
            uint4 e0 = __ldg((const uint4*)(g_embp + xi0 * EMBn + uoff));
            uint4 e1 = __ldg((const uint4*)(g_embp + xi1 * EMBn + uoff));

            float acc[2][4];
            #pragma unroll
            for (int j = 0; j < 2; ++j)
                #pragma unroll
                for (int r = 0; r < 4; ++r) acc[j][r] = 0.f;

            if (t > 0) {
                const u32* hp0 = h0_prev_p + (size_t)fr0 * HPS + uoff;
                const u32* hp1 = h0_prev_p + (size_t)fr1 * HPS + uoff;
                uint4 c0 = __ldcg((const uint4*)hp0);
                uint4 c1 = __ldcg((const uint4*)hp1);
                uint4 n0 = __ldcg((const uint4*)(hp0 + 64));
                uint4 n1 = __ldcg((const uint4*)(hp1 + 64));
                chunk_mma2(e0, e1, Whi, Wlo, bcol, acc);
                #pragma unroll 1
                for (int c = 1; c <= 8; ++c) {
                    uint4 t0 = c0, t1 = c1;
                    if (c + 2 <= 8) {
                        t0 = __ldcg((const uint4*)(hp0 + (c + 1) * 64));
                        t1 = __ldcg((const uint4*)(hp1 + (c + 1) * 64));
                    }
                    chunk_mma2(c0, c1, Whi, Wlo, bcol + c * 32, acc);
                    c0 = n0; c1 = n1; n0 = t0; n1 = t1;
                }
            } else {
                chunk_mma2(e0, e1, Whi, Wlo, bcol, acc);
            }
            epilogue2(acc, red, wid, lane, rbase, l0ba, l0bb, po, h0_cur_p);
        }
        group_sync(grp);

        // ===== layer 1 ====================================================
        {
            const u32* h0c0 = h0_cur_p + (size_t)fr0 * HPS + uoff;
            const u32* h0c1 = h0_cur_p + (size_t)fr1 * HPS + uoff;
            const u32* h1p0 = h1_prev_p + (size_t)fr0 * HPS + uoff;
            const u32* h1p1 = h1_prev_p + (size_t)fr1 * HPS + uoff;
            const int nch = (t == 0) ? 8 : 16;

            float acc[2][4];
            #pragma unroll
            for (int j = 0; j < 2; ++j)
                #pragma unroll
                for (int r = 0; r < 4; ++r) acc[j][r] = 0.f;

            uint4 c0 = __ldcg((const uint4*)h0c0);
            uint4 c1 = __ldcg((const uint4*)h0c1);
            uint4 n0 = __ldcg((const uint4*)(h0c0 + 64));
            uint4 n1 = __ldcg((const uint4*)(h0c1 + 64));
            #pragma unroll 1
            for (int c = 0; c < nch; ++c) {
                uint4 t0 = c0, t1 = c1;
                if (c + 2 < nch) {
                    const int ci = c + 2;
                    const u32* a0 = (ci < 8) ? (h0c0 + ci * 64)
                                             : (h1p0 + (ci - 8) * 64);
                    const u32* a1 = (ci < 8) ? (h0c1 + ci * 64)
                                             : (h1p1 + (ci - 8) * 64);
                    t0 = __ldcg((const uint4*)a0);
                    t1 = __ldcg((const uint4*)a1);
                }
                chunk_mma2(c0, c1, Whi, Wlo, bcol + 288 + c * 32, acc);
                c0 = n0; c1 = n1; n0 = t0; n1 = t1;
            }
            epilogue2(acc, red, wid, lane, rbase, l1ba, l1bb, po, h1_cur_p);
        }
        // no barrier: next step's post-L0 group_sync transitively orders h1.
    }

    grid_sync_all();

    // ===== final FC via tensor cores: logits = h1 @ W_fc + b_fc ==========
    // M = 131072 rows (m = t*256 + b) split across CTAs; 2 passes of 64 cols.
    u32*   Fhi  = smem_u;                      // [64 cols][WS2]
    u32*   Flo  = smem_u + 64 * WS2;
    float* red2 = (float*)(smem_u + 2 * 64 * WS2);   // 16*RS2 floats

    // FC epilogue read mapping: w -> (mh_r2, jg2); thread covers rh 0..1, p 0..1
    const int mh_r2 = wid & 1;
    const int jg2   = (wid >> 1) & 7;
    const int base2 = (mh_r2 + 2 * (jg2 >> 2)) * RS2 + (gr * 4 + ktr) * 21
                    + (jg2 & 3) * 4;

    for (int pass = 0; pass < 2; ++pass) {
        __syncthreads();
        // load W_fc half-columns as packed hi/lo, fragment-permuted
        for (int i = tid; i < 64 * 256; i += BLOCKT) {
            int cc = i & 63;
            int kp = i >> 6;
            float w0 = W_fc[(size_t)(2 * kp) * VSn + pass * 64 + cc];
            float w1 = W_fc[(size_t)(2 * kp + 1) * VSn + pass * 64 + cc];
            u32 hi, lo;
            split2(w0, w1, hi, lo);
            int slot = permslot(kp);
            Fhi[cc * WS2 + slot] = hi;
            Flo[cc * WS2 + slot] = lo;
        }
        __syncthreads();

        const int cfc = pass * 64 + jg2 * 8 + 2 * ktr;
        const float bfa = b_fc[cfc], bfb = b_fc[cfc + 1];

        for (int ti = 0; ti < 32; ++ti) {
            const int m0 = (cta * 32 + ti) * 32;
            const u32* a0p = g_outsp + (size_t)(m0 + mh * 16 + g) * HPS + uoff;
            const u32* a1p = a0p + 8 * HPS;

            float acc[4][4];
            #pragma unroll
            for (int j = 0; j < 4; ++j)
                #pragma unroll
                for (int r = 0; r < 4; ++r) acc[j][r] = 0.f;

            uint4 c0 = *(const uint4*)a0p;
            uint4 c1 = *(const uint4*)a1p;
            #pragma unroll 1
            for (int c = 0; c < 8; ++c) {
                uint4 t0 = c0, t1 = c1;
                if (c + 1 < 8) {
                    t0 = *(const uint4*)(a0p + (c + 1) * 64);
                    t1 = *(const uint4*)(a1p + (c + 1) * 64);
                }
                #pragma unroll
                for (int jl = 0; jl < 4; ++jl) {
                    int bb_ = ((nh * 4 + jl) * 8 + g) * WS2 + c * 32
                            + ks * 8 + 2 * kt;
                    uint2 Bh = *(const uint2*)(Fhi + bb_);
                    uint2 Bl = *(const uint2*)(Flo + bb_);
                    mma16816(acc[jl], c0.x, c1.x, c0.z, c1.z, Bh.x, Bh.y);
                    mma16816(acc[jl], c0.x, c1.x, c0.z, c1.z, Bl.x, Bl.y);
                    mma16816(acc[jl], c0.y, c1.y, c0.w, c1.w, Bh.x, Bh.y);
                }
                c0 = t0; c1 = t1;
            }

            // reduction + store
            {
                float* st = red2 + wid * RS2 + lane * 21;
                #pragma unroll
                for (int jl = 0; jl < 4; ++jl) {
                    st[jl * 4 + 0] = acc[jl][0];
                    st[jl * 4 + 1] = acc[jl][1];
                    st[jl * 4 + 2] = acc[jl][2];
                    st[jl * 4 + 3] = acc[jl][3];
                }
                __syncthreads();
                float r0 = 0.f, r1 = 0.f, r2 = 0.f, r3 = 0.f;
                #pragma unroll
                for (int k = 0; k < 4; ++k) {
                    const float* q = red2 + base2 + k * (4 * RS2);
                    r0 += q[0]; r1 += q[1]; r2 += q[2]; r3 += q[3];
                }
                #pragma unroll
                for (int rh2 = 0; rh2 < 2; ++rh2) {
                    const int m  = m0 + mh_r2 * 16 + rh2 * 8 + gr;
                    const int tt = m >> 8;
                    const int bb = m & 255;
                    float2 v = rh2 ? make_float2(r2 + bfa, r3 + bfb)
                                   : make_float2(r0 + bfa, r1 + bfb);
                    *(float2*)(out + ((size_t)bb * Tn + tt) * VSn + cfc) = v;
                }
                __syncthreads();
            }
        }
    }
}

extern "C" void kernel_launch(void* const* d_in, const int* in_sizes, int n_in,
                              void* d_out, int out_size) {
    const int*   x      = (const int*)  d_in[0];
    const float* emb    = (const float*)d_in[1];
    const float* W_ih0  = (const float*)d_in[2];
    const float* b_ih0  = (const float*)d_in[3];
    const float* W_hh0  = (const float*)d_in[4];
    const float* b_hh0  = (const float*)d_in[5];
    const float* W_ih1  = (const float*)d_in[6];
    const float* b_ih1  = (const float*)d_in[7];
    const float* W_hh1  = (const float*)d_in[8];
    const float* b_hh1  = (const float*)d_in[9];
    const float* W_fc   = (const float*)d_in[10];
    const float* b_fc   = (const float*)d_in[11];
    float* out = (float*)d_out;

    cudaFuncSetAttribute(rnn_persistent_kernel,
                         cudaFuncAttributeMaxDynamicSharedMemorySize, SMEM_BYTES);

    rnn_persistent_kernel<<<GRID, BLOCKT, SMEM_BYTES>>>(
        x, emb, W_ih0, b_ih0, W_hh0, b_hh0,
        W_ih1, b_ih1, W_hh1, b_hh1, W_fc, b_fc, out);
}

// round 10
// speedup vs baseline: 3.2541x; 1.4096x over previous
#include <cuda_runtime.h>
#include <cuda_fp16.h>

// Problem sizes
#define Bn   256
#define Tn   512
#define EMBn 64
#define HSn  512
#define VSn  128

// 8 row-groups (32 batch rows) x 16 col-tiles (32 hidden cols) = 128 CTAs
#define GRID   128
#define NGROUP 8
#define GSIZE  16
#define BLOCKT 512
#define WS     808           // W plane row stride in u32 kpairs (800 + pad)
#define HPS    512           // packed-h row stride in u32 (256 kpairs * 2)
#define RS     296           // recurrence reduction stride
#define WS2    264           // FC B plane row stride
#define RS2    672           // FC reduction stride

#define SMEM_U32   (2 * 32 * WS + 5120)
#define SMEM_BYTES (SMEM_U32 * 4)         // 227,328 B

typedef unsigned int u32;

// -------- persistent device state ----------------------------------------
__device__ u32 g_h0p[2][Bn * HPS];                  // ping-pong packed h0
__device__ u32 g_outsp[(size_t)Tn * Bn * HPS];      // packed h1 history
__device__ u32 g_embp[VSn * EMBn];                  // packed embedding
struct PadCnt { unsigned v; unsigned pad[31]; };
__device__ PadCnt g_gcnt[NGROUP];
__device__ volatile unsigned g_gphase[NGROUP * 32];
__device__ unsigned g_allcnt;
__device__ volatile unsigned g_allphase;

__device__ __forceinline__ void group_sync(int g) {
    __threadfence();
    __syncthreads();
    if (threadIdx.x == 0) {
        unsigned ph = g_gphase[g * 32];
        if (atomicAdd(&g_gcnt[g].v, 1u) == GSIZE - 1u) {
            g_gcnt[g].v = 0u;
            __threadfence();
            g_gphase[g * 32] = ph + 1u;
        } else {
            while (g_gphase[g * 32] == ph) { }
        }
    }
    __syncthreads();
}

__device__ __forceinline__ void grid_sync_all() {
    __threadfence();
    __syncthreads();
    if (threadIdx.x == 0) {
        unsigned ph = g_allphase;
        if (atomicAdd(&g_allcnt, 1u) == GRID - 1u) {
            g_allcnt = 0u;
            __threadfence();
            g_allphase = ph + 1u;
        } else {
            while (g_allphase == ph) { }
        }
    }
    __syncthreads();
}

// -------- fp16 split + mma helpers ---------------------------------------
__device__ __forceinline__ void split2(float x, float y, u32& hi, u32& lo) {
    __half hx = __float2half_rn(x), hy = __float2half_rn(y);
    __half lx = __float2half_rn(x - __half2float(hx));
    __half ly = __float2half_rn(y - __half2float(hy));
    __half2 h = __halves2half2(hx, hy), l = __halves2half2(lx, ly);
    hi = *(u32*)&h; lo = *(u32*)&l;
}

__device__ __forceinline__ int permslot(int kp) {
    int p = kp & 7;
    return (kp & ~7) + ((p < 4) ? 2 * p : 2 * p - 7);
}

__device__ __forceinline__ void mma16816(float c[4],
                                         u32 a0, u32 a1, u32 a2, u32 a3,
                                         u32 b0, u32 b1) {
    asm volatile(
        "mma.sync.aligned.m16n8k16.row.col.f32.f16.f16.f32 "
        "{%0,%1,%2,%3}, {%4,%5,%6,%7}, {%8,%9}, {%0,%1,%2,%3};"
        : "+f"(c[0]), "+f"(c[1]), "+f"(c[2]), "+f"(c[3])
        : "r"(a0), "r"(a1), "r"(a2), "r"(a3), "r"(b0), "r"(b1));
}

// One chunk, this warp's k16 block, 2 n-blocks, 3 split products.
__device__ __forceinline__ void chunk_mma2(uint4 u0, uint4 u1,
                                           const u32* __restrict__ Whi,
                                           const u32* __restrict__ Wlo,
                                           int bbase, float acc[2][4]) {
    #pragma unroll
    for (int jl = 0; jl < 2; ++jl) {
        uint2 Bh = *(const uint2*)(Whi + bbase + jl * (8 * WS));
        uint2 Bl = *(const uint2*)(Wlo + bbase + jl * (8 * WS));
        mma16816(acc[jl], u0.x, u1.x, u0.z, u1.z, Bh.x, Bh.y);  // Ah*Bh
        mma16816(acc[jl], u0.x, u1.x, u0.z, u1.z, Bl.x, Bl.y);  // Ah*Bl
        mma16816(acc[jl], u0.y, u1.y, u0.w, u1.w, Bh.x, Bh.y);  // Al*Bh
    }
}

// Reduction + bias + tanh + packed (hi,lo) store. One uint2 / thread.
// NOTE: no trailing sync — caller provides separation before red reuse.
__device__ __forceinline__ void epilogue_one(float acc[2][4], float* red,
                                             int wid, int lane, int rbase,
                                             float ba, float bb,
                                             size_t po, u32* __restrict__ destp) {
    float* st = red + wid * RS + lane * 9;
    st[0] = acc[0][0]; st[1] = acc[0][1]; st[2] = acc[0][2]; st[3] = acc[0][3];
    st[4] = acc[1][0]; st[5] = acc[1][1]; st[6] = acc[1][2]; st[7] = acc[1][3];
    __syncthreads();
    float s0 = 0.f, s1 = 0.f;
    #pragma unroll
    for (int k = 0; k < 4; ++k) {
        const float* q = red + rbase + k * (4 * RS);
        s0 += q[0]; s1 += q[1];
    }
    u32 hi, lo;
    split2(tanhf(s0 + ba), tanhf(s1 + bb), hi, lo);
    *(uint2*)(destp + po) = make_uint2(hi, lo);
}

// Fused phase: L1(t) [h0(t) @ Wih1 + h1(t-1) @ Whh1] and
//              L0(t+1) [emb(t+1) @ Wih0 + h0(t) @ Whh0].
// A-chunk stream: [emb?] + 8 h0 chunks + [8 h1prev chunks?]. h0 loaded once.
template<bool DOL0, bool DOH1P>
__device__ __forceinline__ void phase_mma(
    int xi0, int xi1,
    const u32* __restrict__ h0c0, const u32* __restrict__ h0c1,
    const u32* __restrict__ h1p0, const u32* __restrict__ h1p1,
    const u32* __restrict__ Whi, const u32* __restrict__ Wlo,
    int bcol, int uoff,
    float aL1[2][4], float aL0[2][4])
{
    constexpr int NCH = (DOL0 ? 9 : 8) + (DOH1P ? 8 : 0);
    auto addr0 = [&](int i) -> const u32* {
        if (DOL0 && i == 0) return g_embp + xi0 * EMBn + uoff;
        int base = DOL0 ? i - 1 : i;
        return (base < 8) ? (h0c0 + base * 64) : (h1p0 + (base - 8) * 64);
    };
    auto addr1 = [&](int i) -> const u32* {
        if (DOL0 && i == 0) return g_embp + xi1 * EMBn + uoff;
        int base = DOL0 ? i - 1 : i;
        return (base < 8) ? (h0c1 + base * 64) : (h1p1 + (base - 8) * 64);
    };
    uint4 cur0 = __ldcg((const uint4*)addr0(0));
    uint4 cur1 = __ldcg((const uint4*)addr1(0));
    uint4 nxt0 = cur0, nxt1 = cur1;
    if (NCH > 1) {
        nxt0 = __ldcg((const uint4*)addr0(1));
        nxt1 = __ldcg((const uint4*)addr1(1));
    }
    #pragma unroll
    for (int i = 0; i < NCH; ++i) {
        uint4 t0 = cur0, t1 = cur1;
        if (i + 2 < NCH) {
            t0 = __ldcg((const uint4*)addr0(i + 2));
            t1 = __ldcg((const uint4*)addr1(i + 2));
        }
        if (DOL0 && i == 0) {
            chunk_mma2(cur0, cur1, Whi, Wlo, bcol, aL0);           // emb @ Wih0
        } else {
            const int base = DOL0 ? i - 1 : i;
            if (base < 8) {
                chunk_mma2(cur0, cur1, Whi, Wlo,
                           bcol + (288 + base * 32), aL1);          // h0 @ Wih1
                if (DOL0)
                    chunk_mma2(cur0, cur1, Whi, Wlo,
                               bcol + (32 + base * 32), aL0);       // h0 @ Whh0
            } else {
                chunk_mma2(cur0, cur1, Whi, Wlo,
                           bcol + (544 + (base - 8) * 32), aL1);    // h1p @ Whh1
            }
        }
        cur0 = nxt0; cur1 = nxt1; nxt0 = t0; nxt1 = t1;
    }
}

extern __shared__ u32 smem_u[];

__global__ void __launch_bounds__(BLOCKT, 1) rnn_persistent_kernel(
    const int*   __restrict__ x,
    const float* __restrict__ emb,
    const float* __restrict__ W_ih0, const float* __restrict__ b_ih0,
    const float* __restrict__ W_hh0, const float* __restrict__ b_hh0,
    const float* __restrict__ W_ih1, const float* __restrict__ b_ih1,
    const float* __restrict__ W_hh1, const float* __restrict__ b_hh1,
    const float* __restrict__ W_fc,  const float* __restrict__ b_fc,
    float* __restrict__ out)
{
    u32*   Whi = smem_u;                       // [32 cols][WS]
    u32*   Wlo = smem_u + 32 * WS;
    float* red = (float*)(smem_u + 64 * WS);   // 5120 floats scratch

    const int tid  = threadIdx.x;
    const int cta  = blockIdx.x;
    const int grp  = cta >> 4;
    const int row0 = grp * 32;
    const int col0 = (cta & 15) * 32;

    // ---- weight slice -> SMEM as fp16 hi/lo, fragment-permuted ----------
    {
        const int c  = tid & 31;
        const int pp = tid >> 5;
        for (int pb = 0; pb < 800; pb += 16) {
            int kp = pb + pp;
            int k  = kp * 2;
            const float* src; int kr;
            if      (k < 64)   { src = W_ih0; kr = k; }
            else if (k < 576)  { src = W_hh0; kr = k - 64; }
            else if (k < 1088) { src = W_ih1; kr = k - 576; }
            else               { src = W_hh1; kr = k - 1088; }
            float w0 = src[(size_t)kr * HSn + col0 + c];
            float w1 = src[(size_t)(kr + 1) * HSn + col0 + c];
            u32 hi, lo;
            split2(w0, w1, hi, lo);
            int pos = permslot(kp);
            Whi[c * WS + pos] = hi;
            Wlo[c * WS + pos] = lo;
        }
    }

    // ---- packed embedding precompute: CTA i owns vocab row i -------------
    if (tid < 32) {
        float w0 = emb[cta * EMBn + 2 * tid];
        float w1 = emb[cta * EMBn + 2 * tid + 1];
        u32 hi, lo;
        split2(w0, w1, hi, lo);
        int slot = permslot(tid);
        g_embp[cta * EMBn + slot * 2]     = hi;
        g_embp[cta * EMBn + slot * 2 + 1] = lo;
    }
    grid_sync_all();

    // ---- warp decomposition: wid = mh + 2*nh + 4*ks ----------------------
    const int wid  = tid >> 5;
    const int lane = tid & 31;
    const int mh   = wid & 1;
    const int nh   = (wid >> 1) & 1;
    const int ks   = wid >> 2;
    const int g    = lane >> 2;
    const int kt   = lane & 3;

    const int fr0  = row0 + mh * 16 + g;
    const int fr1  = fr0 + 8;
    const int uoff = (ks * 8 + 2 * kt) * 2;
    const int bcol = (nh * 16 + g) * WS + 2 * kt + ks * 8;

    // epilogue mapping (validated R8/R9 layout)
    const int mh_r = wid & 1;
    const int jg   = (wid >> 1) & 3;
    const int rh   = wid >> 3;
    const int gr   = lane >> 2, ktr = lane & 3;
    const int er   = row0 + mh_r * 16 + rh * 8 + gr;
    const int ec0  = col0 + jg * 8 + 2 * ktr;
    const size_t po = (size_t)er * HPS + permslot(ec0 >> 1) * 2;
    const int rbase = (mh_r + 2 * (jg >> 1)) * RS + (gr * 4 + ktr) * 9
                    + (jg & 1) * 4 + rh * 2;
    const float l0ba = b_ih0[ec0] + b_hh0[ec0];
    const float l0bb = b_ih0[ec0 + 1] + b_hh0[ec0 + 1];
    const float l1ba = b_ih1[ec0] + b_hh1[ec0];
    const float l1bb = b_ih1[ec0 + 1] + b_hh1[ec0 + 1];

    // ===== pre-loop phase: L0(0) = tanh(emb(0) @ Wih0 + b) ===============
    {
        int xi0 = x[fr0 * Tn + 0];
        int xi1 = x[fr1 * Tn + 0];
        uint4 e0 = __ldcg((const uint4*)(g_embp + xi0 * EMBn + uoff));
        uint4 e1 = __ldcg((const uint4*)(g_embp + xi1 * EMBn + uoff));
        float aL0[2][4];
        #pragma unroll
        for (int j = 0; j < 2; ++j)
            #pragma unroll
            for (int r = 0; r < 4; ++r) aL0[j][r] = 0.f;
        chunk_mma2(e0, e1, Whi, Wlo, bcol, aL0);
        epilogue_one(aL0, red, wid, lane, rbase, l0ba, l0bb, po, g_h0p[0]);
    }
    group_sync(grp);

    // ===== main loop: one fused phase per step ===========================
    for (int t = 0; t < Tn; ++t) {
        const u32* h0cur = g_h0p[t & 1];
        u32*       h0nxt = g_h0p[(t & 1) ^ 1];
        const u32* h1prv = g_outsp + ((long)t - 1) * (long)(Bn * HPS);
        u32*       h1cur = g_outsp + (size_t)t * (Bn * HPS);

        const u32* h0c0 = h0cur + (size_t)fr0 * HPS + uoff;
        const u32* h0c1 = h0cur + (size_t)fr1 * HPS + uoff;
        const u32* h1p0 = h1prv + (size_t)fr0 * HPS + uoff;
        const u32* h1p1 = h1prv + (size_t)fr1 * HPS + uoff;

        int xi0 = 0, xi1 = 0;
        if (t + 1 < Tn) {
            xi0 = x[fr0 * Tn + t + 1];
            xi1 = x[fr1 * Tn + t + 1];
        }

        float aL1[2][4], aL0[2][4];
        #pragma unroll
        for (int j = 0; j < 2; ++j)
            #pragma unroll
            for (int r = 0; r < 4; ++r) { aL1[j][r] = 0.f; aL0[j][r] = 0.f; }

        if (t == 0)
            phase_mma<true, false>(xi0, xi1, h0c0, h0c1, h1p0, h1p1,
                                   Whi, Wlo, bcol, uoff, aL1, aL0);
        else if (t + 1 < Tn)
            phase_mma<true, true>(xi0, xi1, h0c0, h0c1, h1p0, h1p1,
                                  Whi, Wlo, bcol, uoff, aL1, aL0);
        else
            phase_mma<false, true>(xi0, xi1, h0c0, h0c1, h1p0, h1p1,
                                   Whi, Wlo, bcol, uoff, aL1, aL0);

        epilogue_one(aL1, red, wid, lane, rbase, l1ba, l1bb, po, h1cur);
        if (t + 1 < Tn) {
            __syncthreads();   // red reuse
            epilogue_one(aL0, red, wid, lane, rbase, l0ba, l0bb, po, h0nxt);
        }
        group_sync(grp);       // h1(t), h0(t+1) visible group-wide
    }

    grid_sync_all();

    // ===== final FC via tensor cores: logits = h1 @ W_fc + b_fc ==========
    u32*   Fhi  = smem_u;                      // [64 cols][WS2]
    u32*   Flo  = smem_u + 64 * WS2;
    float* red2 = (float*)(smem_u + 2 * 64 * WS2);

    const int mh_r2 = wid & 1;
    const int jg2   = (wid >> 1) & 7;
    const int base2 = (mh_r2 + 2 * (jg2 >> 2)) * RS2 + (gr * 4 + ktr) * 21
                    + (jg2 & 3) * 4;

    for (int pass = 0; pass < 2; ++pass) {
        __syncthreads();
        for (int i = tid; i < 64 * 256; i += BLOCKT) {
            int cc = i & 63;
            int kp = i >> 6;
            float w0 = W_fc[(size_t)(2 * kp) * VSn + pass * 64 + cc];
            float w1 = W_fc[(size_t)(2 * kp + 1) * VSn + pass * 64 + cc];
            u32 hi, lo;
            split2(w0, w1, hi, lo);
            int slot = permslot(kp);
            Fhi[cc * WS2 + slot] = hi;
            Flo[cc * WS2 + slot] = lo;
        }
        __syncthreads();

        const int cfc = pass * 64 + jg2 * 8 + 2 * ktr;
        const float bfa = b_fc[cfc], bfb = b_fc[cfc + 1];

        for (int ti = 0; ti < 32; ++ti) {
            const int m0 = (cta * 32 + ti) * 32;
            const u32* a0p = g_outsp + (size_t)(m0 + mh * 16 + g) * HPS + uoff;
            const u32* a1p = a0p + 8 * HPS;

            float acc[4][4];
            #pragma unroll
            for (int j = 0; j < 4; ++j)
                #pragma unroll
                for (int r = 0; r < 4; ++r) acc[j][r] = 0.f;

            uint4 c0 = *(const uint4*)a0p;
            uint4 c1 = *(const uint4*)a1p;
            #pragma unroll 1
            for (int c = 0; c < 8; ++c) {
                uint4 t0 = c0, t1 = c1;
                if (c + 1 < 8) {
                    t0 = *(const uint4*)(a0p + (c + 1) * 64);
                    t1 = *(const uint4*)(a1p + (c + 1) * 64);
                }
                #pragma unroll
                for (int jl = 0; jl < 4; ++jl) {
                    int bb_ = ((nh * 4 + jl) * 8 + g) * WS2 + c * 32
                            + ks * 8 + 2 * kt;
                    uint2 Bh = *(const uint2*)(Fhi + bb_);
                    uint2 Bl = *(const uint2*)(Flo + bb_);
                    mma16816(acc[jl], c0.x, c1.x, c0.z, c1.z, Bh.x, Bh.y);
                    mma16816(acc[jl], c0.x, c1.x, c0.z, c1.z, Bl.x, Bl.y);
                    mma16816(acc[jl], c0.y, c1.y, c0.w, c1.w, Bh.x, Bh.y);
                }
                c0 = t0; c1 = t1;
            }

            {
                float* st = red2 + wid * RS2 + lane * 21;
                #pragma unroll
                for (int jl = 0; jl < 4; ++jl) {
                    st[jl * 4 + 0] = acc[jl][0];
                    st[jl * 4 + 1] = acc[jl][1];
                    st[jl * 4 + 2] = acc[jl][2];
                    st[jl * 4 + 3] = acc[jl][3];
                }
                __syncthreads();
                float r0 = 0.f, r1 = 0.f, r2 = 0.f, r3 = 0.f;
                #pragma unroll
                for (int k = 0; k < 4; ++k) {
                    const float* q = red2 + base2 + k * (4 * RS2);
                    r0 += q[0]; r1 += q[1]; r2 += q[2]; r3 += q[3];
                }
                #pragma unroll
                for (int rh2 = 0; rh2 < 2; ++rh2) {
                    const int m  = m0 + mh_r2 * 16 + rh2 * 8 + gr;
                    const int tt = m >> 8;
                    const int bb = m & 255;
                    float2 v = rh2 ? make_float2(r2 + bfa, r3 + bfb)
                                   : make_float2(r0 + bfa, r1 + bfb);
                    *(float2*)(out + ((size_t)bb * Tn + tt) * VSn + cfc) = v;
                }
                __syncthreads();
            }
        }
    }
}

extern "C" void kernel_launch(void* const* d_in, const int* in_sizes, int n_in,
                              void* d_out, int out_size) {
    const int*   x      = (const int*)  d_in[0];
    const float* emb    = (const float*)d_in[1];
    const float* W_ih0  = (const float*)d_in[2];
    const float* b_ih0  = (const float*)d_in[3];
    const float* W_hh0  = (const float*)d_in[4];
    const float* b_hh0  = (const float*)d_in[5];
    const float* W_ih1  = (const float*)d_in[6];
    const float* b_ih1  = (const float*)d_in[7];
    const float* W_hh1  = (const float*)d_in[8];
    const float* b_hh1  = (const float*)d_in[9];
    const float* W_fc   = (const float*)d_in[10];
    const float* b_fc   = (const float*)d_in[11];
    float* out = (float*)d_out;

    cudaFuncSetAttribute(rnn_persistent_kernel,
                         cudaFuncAttributeMaxDynamicSharedMemorySize, SMEM_BYTES);

    rnn_persistent_kernel<<<GRID, BLOCKT, SMEM_BYTES>>>(
        x, emb, W_ih0, b_ih0, W_hh0, b_hh0,
        W_ih1, b_ih1, W_hh1, b_hh1, W_fc, b_fc, out);
}